// round 12
// baseline (speedup 1.0000x reference)
#include <cuda_runtime.h>
#include <cuda_fp16.h>
#include <mma.h>
#include <cstdint>

using namespace nvcuda;

#define BATCH   2
#define SEQ     8192
#define DMODEL  1024
#define NHEADS  16
#define HD      64
#define NBLK    64
#define BS      128

#define QKV_SEG ((size_t)BATCH * NHEADS * SEQ * HD)   // 16M halves per segment

// ---------------------------------------------------------------------------
// Device scratch
// ---------------------------------------------------------------------------
__device__ __half g_xh[(size_t)BATCH * SEQ * DMODEL];      // fp16 x
__device__ __half g_wqkv[(size_t)3 * DMODEL * DMODEL];     // Wq|Wk|Wv concat (N-dim)
__device__ __half g_wo[(size_t)DMODEL * DMODEL];
__device__ __half g_qkvh[3 * QKV_SEG];                     // q|k|v fp16
__device__ __half g_attnh[(size_t)BATCH * SEQ * DMODEL];   // fp16 attn out

// ---------------------------------------------------------------------------
// conversion kernels
// ---------------------------------------------------------------------------
__global__ void f2h_kernel(const float* __restrict__ src, __half* __restrict__ dst, int n4)
{
    int i = blockIdx.x * blockDim.x + threadIdx.x;
    for (; i < n4; i += gridDim.x * blockDim.x) {
        float4 v = *(const float4*)(src + (size_t)i * 4);
        __half2 lo = __floats2half2_rn(v.x, v.y);
        __half2 hi = __floats2half2_rn(v.z, v.w);
        uint2 o;
        o.x = *(uint32_t*)&lo;
        o.y = *(uint32_t*)&hi;
        *(uint2*)(dst + (size_t)i * 4) = o;
    }
}

__global__ void f2h3_kernel(const float* __restrict__ s0, const float* __restrict__ s1,
                            const float* __restrict__ s2, __half* __restrict__ dst)
{
    const int seg4 = (DMODEL * DMODEL) / 4;   // 262144
    int i = blockIdx.x * blockDim.x + threadIdx.x;
    for (; i < 3 * seg4; i += gridDim.x * blockDim.x) {
        int which = i / seg4;
        int loc = i - which * seg4;
        const float* src = (which == 0) ? s0 : (which == 1) ? s1 : s2;
        float4 v = *(const float4*)(src + (size_t)loc * 4);
        __half2 lo = __floats2half2_rn(v.x, v.y);
        __half2 hi = __floats2half2_rn(v.z, v.w);
        uint2 o;
        o.x = *(uint32_t*)&lo;
        o.y = *(uint32_t*)&hi;
        *(uint2*)(dst + (size_t)i * 4) = o;
    }
}

// ---------------------------------------------------------------------------
// cp.async helpers
// ---------------------------------------------------------------------------
__device__ __forceinline__ uint32_t smem_u32(const void* p) {
    uint32_t a;
    asm("{ .reg .u64 t; cvta.to.shared.u64 t, %1; cvt.u32.u64 %0, t; }" : "=r"(a) : "l"(p));
    return a;
}
#define CP_ASYNC16(dst, src) \
    asm volatile("cp.async.cg.shared.global [%0], [%1], 16;" :: "r"(dst), "l"(src))
#define CP_ASYNC16Z(dst, src, sz) \
    asm volatile("cp.async.cg.shared.global [%0], [%1], 16, %2;" :: "r"(dst), "l"(src), "r"(sz))
#define CP_COMMIT() asm volatile("cp.async.commit_group;")
#define CP_WAIT(N)  asm volatile("cp.async.wait_group %0;" :: "n"(N) : "memory")

// ---------------------------------------------------------------------------
// fp16 GEMM v4: BM=BN=128, BK=64, 128 threads, 4 warps (2x2), warp 64x64,
// 3-stage cp.async, 110.6KB smem, 2 CTAs/SM. 16 mainloop iterations.
// LAYOUT 0: C fp32 row-major [M,N] (N=1024), bias = b0
// LAYOUT 1: C half, fused QKV (N=3072), bias segment from b0/b1/b2
// ---------------------------------------------------------------------------
#define BKH   64
#define LDH   72                                  // 64 + 8 pad (halves)
#define NST   3
#define NCH   (DMODEL / BKH)                      // 16
#define TILE_HBYTES (128 * LDH * 2)               // 18432
#define STAGE_BYTES (2 * TILE_HBYTES)             // 36864
#define GEMM_SMEM   (NST * STAGE_BYTES)           // 110592

template <int LAYOUT>
__global__ void __launch_bounds__(128, 2)
gemm_h_kernel(const __half* __restrict__ A, const __half* __restrict__ W,
              const float* __restrict__ b0, const float* __restrict__ b1,
              const float* __restrict__ b2, void* __restrict__ Cv)
{
    extern __shared__ __align__(128) char smem[];
    const uint32_t sbase = smem_u32(smem);
    const int tid  = threadIdx.x;
    const int warp = tid >> 5;
    const int wm   = warp & 1;      // 2 row groups of 64
    const int wn   = warp >> 1;     // 2 col groups of 64
    const int m0   = blockIdx.y * 128;
    const int n0   = blockIdx.x * 128;

    const __half* Abase = A + (size_t)m0 * DMODEL;
    const __half* Bbase = W + (size_t)n0 * DMODEL;

    wmma::fragment<wmma::accumulator, 16, 16, 16, float> acc[4][4];
#pragma unroll
    for (int i = 0; i < 4; i++)
#pragma unroll
        for (int j = 0; j < 4; j++)
            wmma::fill_fragment(acc[i][j], 0.0f);

    auto load_stage = [&](int c, int s) {
        const int k0 = c * BKH;
        uint32_t sa = sbase + s * STAGE_BYTES;
        // A: 128 rows x 8 chunks of 8 halves = 1024 cp.async (8/thread)
#pragma unroll
        for (int i = 0; i < 8; i++) {
            int idx = tid + i * 128;
            int r = idx >> 3, ch = (idx & 7) << 3;
            CP_ASYNC16(sa + (r * LDH + ch) * 2,
                       Abase + (size_t)r * DMODEL + k0 + ch);
        }
#pragma unroll
        for (int i = 0; i < 8; i++) {
            int idx = tid + i * 128;
            int r = idx >> 3, ch = (idx & 7) << 3;
            CP_ASYNC16(sa + TILE_HBYTES + (r * LDH + ch) * 2,
                       Bbase + (size_t)r * DMODEL + k0 + ch);
        }
    };

    load_stage(0, 0); CP_COMMIT();
    load_stage(1, 1); CP_COMMIT();

    for (int c = 0; c < NCH; c++) {
        const int s = c % NST;
        CP_WAIT(1);
        __syncthreads();

        if (c + NST - 1 < NCH) load_stage(c + NST - 1, (c + NST - 1) % NST);
        CP_COMMIT();

        const __half* As = (const __half*)(smem + s * STAGE_BYTES);
        const __half* Bs = (const __half*)(smem + s * STAGE_BYTES + TILE_HBYTES);
#pragma unroll
        for (int ks = 0; ks < BKH / 16; ks++) {
            wmma::fragment<wmma::matrix_a, 16, 16, 16, __half, wmma::row_major> af[4];
#pragma unroll
            for (int i = 0; i < 4; i++)
                wmma::load_matrix_sync(af[i], As + (wm * 64 + i * 16) * LDH + ks * 16, LDH);
#pragma unroll
            for (int j = 0; j < 4; j++) {
                wmma::fragment<wmma::matrix_b, 16, 16, 16, __half, wmma::col_major> bf;
                wmma::load_matrix_sync(bf, Bs + (wn * 64 + j * 16) * LDH + ks * 16, LDH);
#pragma unroll
                for (int i = 0; i < 4; i++)
                    wmma::mma_sync(acc[i][j], af[i], bf, acc[i][j]);
            }
        }
        // no trailing barrier: next top-of-loop __syncthreads orders stage reuse
    }

    CP_WAIT(0);
    __syncthreads();

    float* stg = (float*)smem;   // 128 x 132 fp32 = 67584 <= 110592
#pragma unroll
    for (int i = 0; i < 4; i++)
#pragma unroll
        for (int j = 0; j < 4; j++)
            wmma::store_matrix_sync(&stg[(wm * 64 + i * 16) * 132 + wn * 64 + j * 16],
                                    acc[i][j], 132, wmma::mem_row_major);
    __syncthreads();

    // bias pointer + segment (uniform per CTA for LAYOUT 1: n0 is 128-aligned)
    const int which = n0 >> 10;
    const float* bp = (LAYOUT == 0) ? b0
                      : (which == 0 ? b0 : (which == 1 ? b1 : b2));
    const int nseg = (LAYOUT == 0) ? n0 : (n0 & 1023);

#pragma unroll
    for (int i = 0; i < 32; i++) {
        int idx = tid + i * 128;        // 4096 quads = 128 x 32
        int r   = idx >> 5;
        int c4  = (idx & 31) << 2;
        float4 v = *(float4*)&stg[r * 132 + c4];
        float4 bv = *(const float4*)&bp[nseg + c4];
        v.x += bv.x; v.y += bv.y; v.z += bv.z; v.w += bv.w;

        if (LAYOUT == 0) {
            float* C = (float*)Cv;
            *(float4*)&C[(size_t)(m0 + r) * DMODEL + n0 + c4] = v;
        } else {
            __half* C = (__half*)Cv;
            int m  = m0 + r;
            int bb = m >> 13;
            int ss = m & (SEQ - 1);
            int nl = nseg + c4;
            int hh = nl >> 6;
            int d0 = nl & 63;
            __half2 lo = __floats2half2_rn(v.x, v.y);
            __half2 hi = __floats2half2_rn(v.z, v.w);
            uint2 o; o.x = *(uint32_t*)&lo; o.y = *(uint32_t*)&hi;
            *(uint2*)&C[(size_t)which * QKV_SEG +
                        (((size_t)bb * NHEADS + hh) * SEQ + ss) * HD + d0] = o;
        }
    }
}

// ---------------------------------------------------------------------------
// Pipelined streaming fp16 attention (validated round-10 version).
// ---------------------------------------------------------------------------
#define WKB 64
#define NJ  6
#define SCLD 68
#define PLD  72
#define KVLD 72
#define KVBUF_BYTES (2 * WKB * KVLD * 2)          // 18432
#define OFF_PH  (128 * SCLD * 4)                  // 34816
#define OFF_KV0 (OFF_PH + 128 * PLD * 2)          // 53248
#define OFF_KV1 (OFF_KV0 + KVBUF_BYTES)           // 71680
#define OFF_RS  (OFF_KV1 + KVBUF_BYTES)           // 90112
#define ATTN_SMEM (OFF_RS + 512)                  // 90624

__global__ void __launch_bounds__(256)
attn_kernel(const __half* __restrict__ Q, const __half* __restrict__ K,
            const __half* __restrict__ V, __half* __restrict__ O)
{
    extern __shared__ __align__(128) char smem[];
    const uint32_t sbase = smem_u32(smem);
    float*  Sc   = (float*)smem;                  // [128][68]
    __half* Ph   = (__half*)(smem + OFF_PH);      // [128][72]
    float*  rsum = (float*)(smem + OFF_RS);       // [128]

    const int tid  = threadIdx.x;
    const int warp = tid >> 5;
    const int n    = blockIdx.x & 63;
    const int h    = (blockIdx.x >> 6) & 15;
    const int b    = blockIdx.x >> 10;
    const size_t base = ((size_t)(b * NHEADS + h)) * SEQ * HD;
    const int kbase = (n - 1) * BS;

    auto load_kv = [&](int j, uint32_t koff) {
        const int kblk = kbase + j * WKB;
#pragma unroll
        for (int i = 0; i < 2; i++) {
            int idx = tid + i * 256;
            int r = idx >> 3, ch = (idx & 7) << 3;
            int kpos = kblk + r;
            bool ok = (kpos >= 0 && kpos < SEQ);
            uint32_t sz = ok ? 16u : 0u;
            size_t off = ok ? (base + (size_t)kpos * HD + ch) : base;
            CP_ASYNC16Z(koff + (r * KVLD + ch) * 2, K + off, sz);
            CP_ASYNC16Z(koff + WKB * KVLD * 2 + (r * KVLD + ch) * 2, V + off, sz);
        }
    };

    {
        const __half* qb = Q + base + (size_t)(n * BS) * HD;
#pragma unroll
        for (int i = 0; i < 4; i++) {
            int idx = tid + i * 256;
            int r = idx >> 3, ch = (idx & 7) << 3;
            *(uint4*)(Ph + r * PLD + ch) = *(const uint4*)(qb + (size_t)r * HD + ch);
        }
    }
    __syncthreads();

    wmma::fragment<wmma::matrix_a, 16, 16, 16, __half, wmma::row_major> qf[4];
#pragma unroll
    for (int ks = 0; ks < 4; ks++)
        wmma::load_matrix_sync(qf[ks], Ph + (warp * 16) * PLD + ks * 16, PLD);
    __syncthreads();

    const int qrow = tid >> 1;
    const int par  = tid & 1;
    int klo = qrow;
    if (kbase < 0 && -kbase > klo) klo = -kbase;
    int khi = qrow + 256;
    {
        int lim = SEQ - kbase - 1;
        if (lim < khi) khi = lim;
    }
    float lsum = 0.f;

    wmma::fragment<wmma::accumulator, 16, 16, 16, float> of[4];
#pragma unroll
    for (int dt = 0; dt < 4; dt++) wmma::fill_fragment(of[dt], 0.0f);

    load_kv(0, sbase + OFF_KV0);
    CP_COMMIT();

    for (int j = 0; j < NJ; j++) {
        const uint32_t koff = sbase + ((j & 1) ? OFF_KV1 : OFF_KV0);

        CP_WAIT(0);
        __syncthreads();

        if (j + 1 < NJ) {
            load_kv(j + 1, sbase + (((j + 1) & 1) ? OFF_KV1 : OFF_KV0));
            CP_COMMIT();
        }

        const __half* Kb = (const __half*)(smem + (koff - sbase));
        const __half* Vb = Kb + WKB * KVLD;

#pragma unroll
        for (int nt = 0; nt < 4; nt++) {
            wmma::fragment<wmma::accumulator, 16, 16, 16, float> sacc;
            wmma::fill_fragment(sacc, 0.0f);
#pragma unroll
            for (int ks = 0; ks < 4; ks++) {
                wmma::fragment<wmma::matrix_b, 16, 16, 16, __half, wmma::col_major> bf;
                wmma::load_matrix_sync(bf, Kb + (nt * 16) * KVLD + ks * 16, KVLD);
                wmma::mma_sync(sacc, qf[ks], bf, sacc);
            }
            wmma::store_matrix_sync(&Sc[(warp * 16) * SCLD + nt * 16], sacc,
                                    SCLD, wmma::mem_row_major);
        }
        __syncwarp();

        {
            float* row = &Sc[qrow * SCLD];
            __half* prow = Ph + qrow * PLD;
            const int c0 = par * 32;
#pragma unroll
            for (int c4 = 0; c4 < 32; c4 += 4) {
                int c = c0 + c4;
                float4 v = *(float4*)&row[c];
                float p0 = 0.f, p1 = 0.f, p2 = 0.f, p3 = 0.f;
                int kk = j * WKB + c;
                if (kk + 0 >= klo && kk + 0 <= khi) p0 = __expf(v.x * 0.125f);
                if (kk + 1 >= klo && kk + 1 <= khi) p1 = __expf(v.y * 0.125f);
                if (kk + 2 >= klo && kk + 2 <= khi) p2 = __expf(v.z * 0.125f);
                if (kk + 3 >= klo && kk + 3 <= khi) p3 = __expf(v.w * 0.125f);
                lsum += p0 + p1 + p2 + p3;
                __half2 lo = __floats2half2_rn(p0, p1);
                __half2 hi = __floats2half2_rn(p2, p3);
                uint2 o; o.x = *(uint32_t*)&lo; o.y = *(uint32_t*)&hi;
                *(uint2*)&prow[c] = o;
            }
        }
        __syncwarp();

#pragma unroll
        for (int ks = 0; ks < 4; ks++) {
            wmma::fragment<wmma::matrix_a, 16, 16, 16, __half, wmma::row_major> pf;
            wmma::load_matrix_sync(pf, Ph + (warp * 16) * PLD + ks * 16, PLD);
#pragma unroll
            for (int dt = 0; dt < 4; dt++) {
                wmma::fragment<wmma::matrix_b, 16, 16, 16, __half, wmma::row_major> vf;
                wmma::load_matrix_sync(vf, Vb + (ks * 16) * KVLD + dt * 16, KVLD);
                wmma::mma_sync(of[dt], pf, vf, of[dt]);
            }
        }
    }

    lsum += __shfl_xor_sync(0xFFFFFFFF, lsum, 1);
    if (par == 0) rsum[qrow] = 1.0f / lsum;

#pragma unroll
    for (int dt = 0; dt < 4; dt++)
        wmma::store_matrix_sync(&Sc[(warp * 16) * SCLD + dt * 16], of[dt],
                                SCLD, wmma::mem_row_major);
    __syncthreads();

#pragma unroll
    for (int i = 0; i < 4; i++) {
        int idx = tid + i * 256;
        int r = idx >> 3, ch = (idx & 7) << 3;
        float s = rsum[r];
        float4 f0 = *(float4*)&Sc[r * SCLD + ch];
        float4 f1 = *(float4*)&Sc[r * SCLD + ch + 4];
        __half2 a = __floats2half2_rn(f0.x * s, f0.y * s);
        __half2 bb2 = __floats2half2_rn(f0.z * s, f0.w * s);
        __half2 cc = __floats2half2_rn(f1.x * s, f1.y * s);
        __half2 d = __floats2half2_rn(f1.z * s, f1.w * s);
        uint4 o;
        o.x = *(uint32_t*)&a; o.y = *(uint32_t*)&bb2;
        o.z = *(uint32_t*)&cc; o.w = *(uint32_t*)&d;
        *(uint4*)&O[((size_t)b * SEQ + (size_t)n * BS + r) * DMODEL + h * HD + ch] = o;
    }
}

// ---------------------------------------------------------------------------
// Launch
// ---------------------------------------------------------------------------
extern "C" void kernel_launch(void* const* d_in, const int* in_sizes, int n_in,
                              void* d_out, int out_size)
{
    const float* x  = (const float*)d_in[0];
    const float* Wq = (const float*)d_in[1];
    const float* bq = (const float*)d_in[2];
    const float* Wk = (const float*)d_in[3];
    const float* bk = (const float*)d_in[4];
    const float* Wv = (const float*)d_in[5];
    const float* bv = (const float*)d_in[6];
    const float* Wo = (const float*)d_in[7];
    const float* bo = (const float*)d_in[8];
    float* out = (float*)d_out;

    __half *xh, *wqkv, *wo, *ah, *qkv;
    cudaGetSymbolAddress((void**)&xh,   g_xh);
    cudaGetSymbolAddress((void**)&wqkv, g_wqkv);
    cudaGetSymbolAddress((void**)&wo,   g_wo);
    cudaGetSymbolAddress((void**)&ah,   g_attnh);
    cudaGetSymbolAddress((void**)&qkv,  g_qkvh);

    cudaFuncSetAttribute(gemm_h_kernel<0>,
                         cudaFuncAttributeMaxDynamicSharedMemorySize, GEMM_SMEM);
    cudaFuncSetAttribute(gemm_h_kernel<1>,
                         cudaFuncAttributeMaxDynamicSharedMemorySize, GEMM_SMEM);
    cudaFuncSetAttribute(attn_kernel,
                         cudaFuncAttributeMaxDynamicSharedMemorySize, ATTN_SMEM);

    const int XN4 = (BATCH * SEQ * DMODEL) / 4;
    const int WN4 = (DMODEL * DMODEL) / 4;
    f2h_kernel<<<1184, 256>>>(x, xh, XN4);
    f2h3_kernel<<<1184, 256>>>(Wq, Wk, Wv, wqkv);
    f2h_kernel<<<592, 256>>>(Wo, wo, WN4);

    // Fused QKV projection: N = 3072
    dim3 qgrid(3 * DMODEL / 128, (BATCH * SEQ) / 128);   // (24,128)
    gemm_h_kernel<1><<<qgrid, 128, GEMM_SMEM>>>(xh, wqkv, bq, bk, bv, qkv);

    attn_kernel<<<BATCH * NHEADS * NBLK, 256, ATTN_SMEM>>>(
        qkv, qkv + QKV_SEG, qkv + 2 * QKV_SEG, ah);

    dim3 ogrid(DMODEL / 128, (BATCH * SEQ) / 128);       // (8,128)
    gemm_h_kernel<0><<<ogrid, 128, GEMM_SMEM>>>(ah, wo, bo, bo, bo, out);
}

// round 13
// speedup vs baseline: 1.0441x; 1.0441x over previous
#include <cuda_runtime.h>
#include <cuda_fp16.h>
#include <mma.h>
#include <cstdint>

using namespace nvcuda;

#define BATCH   2
#define SEQ     8192
#define DMODEL  1024
#define NHEADS  16
#define HD      64
#define NBLK    64
#define BS      128

#define QKV_SEG ((size_t)BATCH * NHEADS * SEQ * HD)   // 16M halves per segment

// ---------------------------------------------------------------------------
// Device scratch
// ---------------------------------------------------------------------------
__device__ __half g_xh[(size_t)BATCH * SEQ * DMODEL];      // fp16 x
__device__ __half g_wqkv[(size_t)3 * DMODEL * DMODEL];     // Wq|Wk|Wv concat (N-dim)
__device__ __half g_wo[(size_t)DMODEL * DMODEL];
__device__ __half g_qkvh[3 * QKV_SEG];                     // q|k|v fp16
__device__ __half g_attnh[(size_t)BATCH * SEQ * DMODEL];   // fp16 attn out

// ---------------------------------------------------------------------------
// merged conversion kernel: x -> g_xh, Wq|Wk|Wv -> g_wqkv, Wo -> g_wo
// job space in float4 units: [0, XN4) x | [XN4, XN4+3*WN4) wqkv | rest wo
// ---------------------------------------------------------------------------
#define XN4 ((BATCH * SEQ * DMODEL) / 4)          // 4194304
#define WN4 ((DMODEL * DMODEL) / 4)               // 262144
#define TOTAL4 (XN4 + 4 * WN4)

__global__ void convert_all_kernel(const float* __restrict__ x,
                                   const float* __restrict__ Wq,
                                   const float* __restrict__ Wk,
                                   const float* __restrict__ Wv,
                                   const float* __restrict__ Wo)
{
    __half* xh;
    {  // symbol addresses resolve at compile time for __device__ globals
    }
    int i = blockIdx.x * blockDim.x + threadIdx.x;
    for (; i < TOTAL4; i += gridDim.x * blockDim.x) {
        const float* src;
        __half* dst;
        int loc;
        if (i < XN4) {
            src = x; dst = g_xh; loc = i;
        } else if (i < XN4 + 3 * WN4) {
            int j = i - XN4;
            int which = j / WN4;
            loc = j - which * WN4;
            src = (which == 0) ? Wq : (which == 1) ? Wk : Wv;
            dst = g_wqkv + (size_t)which * (DMODEL * DMODEL);
        } else {
            loc = i - XN4 - 3 * WN4;
            src = Wo; dst = g_wo;
        }
        float4 v = *(const float4*)(src + (size_t)loc * 4);
        __half2 lo = __floats2half2_rn(v.x, v.y);
        __half2 hi = __floats2half2_rn(v.z, v.w);
        uint2 o;
        o.x = *(uint32_t*)&lo;
        o.y = *(uint32_t*)&hi;
        *(uint2*)(dst + (size_t)loc * 4) = o;
    }
}

// ---------------------------------------------------------------------------
// cp.async helpers
// ---------------------------------------------------------------------------
__device__ __forceinline__ uint32_t smem_u32(const void* p) {
    uint32_t a;
    asm("{ .reg .u64 t; cvta.to.shared.u64 t, %1; cvt.u32.u64 %0, t; }" : "=r"(a) : "l"(p));
    return a;
}
#define CP_ASYNC16(dst, src) \
    asm volatile("cp.async.cg.shared.global [%0], [%1], 16;" :: "r"(dst), "l"(src))
#define CP_ASYNC16Z(dst, src, sz) \
    asm volatile("cp.async.cg.shared.global [%0], [%1], 16, %2;" :: "r"(dst), "l"(src), "r"(sz))
#define CP_COMMIT() asm volatile("cp.async.commit_group;")
#define CP_WAIT(N)  asm volatile("cp.async.wait_group %0;" :: "n"(N) : "memory")

// ---------------------------------------------------------------------------
// fp16 GEMM (round-11 best + deeper pipeline): BM=BN=128, BK=32, 128 threads,
// 4 warps (2x2), warp 64x64, 5-stage cp.async, 102.4KB smem, 2 CTAs/SM.
// LAYOUT 0: C fp32 row-major [M,N] (N=1024), bias = b0
// LAYOUT 1: C half, fused QKV (N=3072), bias segment from b0/b1/b2
// ---------------------------------------------------------------------------
#define BKH   32
#define LDH   40                                  // 32 + 8 pad (halves)
#define NST   5
#define NCH   (DMODEL / BKH)                      // 32
#define TILE_HBYTES (128 * LDH * 2)               // 10240
#define STAGE_BYTES (2 * TILE_HBYTES)             // 20480
#define GEMM_SMEM   (NST * STAGE_BYTES)           // 102400

template <int LAYOUT>
__global__ void __launch_bounds__(128, 2)
gemm_h_kernel(const __half* __restrict__ A, const __half* __restrict__ W,
              const float* __restrict__ b0, const float* __restrict__ b1,
              const float* __restrict__ b2, void* __restrict__ Cv)
{
    extern __shared__ __align__(128) char smem[];
    const uint32_t sbase = smem_u32(smem);
    const int tid  = threadIdx.x;
    const int warp = tid >> 5;
    const int wm   = warp & 1;      // 2 row groups of 64
    const int wn   = warp >> 1;     // 2 col groups of 64
    const int m0   = blockIdx.y * 128;
    const int n0   = blockIdx.x * 128;

    const __half* Abase = A + (size_t)m0 * DMODEL;
    const __half* Bbase = W + (size_t)n0 * DMODEL;

    wmma::fragment<wmma::accumulator, 16, 16, 16, float> acc[4][4];
#pragma unroll
    for (int i = 0; i < 4; i++)
#pragma unroll
        for (int j = 0; j < 4; j++)
            wmma::fill_fragment(acc[i][j], 0.0f);

    auto load_stage = [&](int c, int s) {
        const int k0 = c * BKH;
        uint32_t sa = sbase + s * STAGE_BYTES;
        // A: 128 rows x 4 chunks of 8 halves = 512 cp.async (4/thread)
#pragma unroll
        for (int i = 0; i < 4; i++) {
            int idx = tid + i * 128;
            int r = idx >> 2, ch = (idx & 3) << 3;
            CP_ASYNC16(sa + (r * LDH + ch) * 2,
                       Abase + (size_t)r * DMODEL + k0 + ch);
        }
#pragma unroll
        for (int i = 0; i < 4; i++) {
            int idx = tid + i * 128;
            int r = idx >> 2, ch = (idx & 3) << 3;
            CP_ASYNC16(sa + TILE_HBYTES + (r * LDH + ch) * 2,
                       Bbase + (size_t)r * DMODEL + k0 + ch);
        }
    };

    load_stage(0, 0); CP_COMMIT();
    load_stage(1, 1); CP_COMMIT();
    load_stage(2, 2); CP_COMMIT();
    load_stage(3, 3); CP_COMMIT();

    for (int c = 0; c < NCH; c++) {
        const int s = c % NST;
        CP_WAIT(3);
        __syncthreads();

        if (c + NST - 1 < NCH) load_stage(c + NST - 1, (c + NST - 1) % NST);
        CP_COMMIT();

        const __half* As = (const __half*)(smem + s * STAGE_BYTES);
        const __half* Bs = (const __half*)(smem + s * STAGE_BYTES + TILE_HBYTES);
#pragma unroll
        for (int ks = 0; ks < BKH / 16; ks++) {
            wmma::fragment<wmma::matrix_a, 16, 16, 16, __half, wmma::row_major> af[4];
#pragma unroll
            for (int i = 0; i < 4; i++)
                wmma::load_matrix_sync(af[i], As + (wm * 64 + i * 16) * LDH + ks * 16, LDH);
#pragma unroll
            for (int j = 0; j < 4; j++) {
                wmma::fragment<wmma::matrix_b, 16, 16, 16, __half, wmma::col_major> bf;
                wmma::load_matrix_sync(bf, Bs + (wn * 64 + j * 16) * LDH + ks * 16, LDH);
#pragma unroll
                for (int i = 0; i < 4; i++)
                    wmma::mma_sync(acc[i][j], af[i], bf, acc[i][j]);
            }
        }
        // no trailing barrier: next top-of-loop __syncthreads orders stage reuse
    }

    CP_WAIT(0);
    __syncthreads();

    float* stg = (float*)smem;   // 128 x 132 fp32 = 67584 <= 102400
#pragma unroll
    for (int i = 0; i < 4; i++)
#pragma unroll
        for (int j = 0; j < 4; j++)
            wmma::store_matrix_sync(&stg[(wm * 64 + i * 16) * 132 + wn * 64 + j * 16],
                                    acc[i][j], 132, wmma::mem_row_major);
    __syncthreads();

    // bias pointer + segment (uniform per CTA for LAYOUT 1: n0 is 128-aligned)
    const int which = n0 >> 10;
    const float* bp = (LAYOUT == 0) ? b0
                      : (which == 0 ? b0 : (which == 1 ? b1 : b2));
    const int nseg = (LAYOUT == 0) ? n0 : (n0 & 1023);

#pragma unroll
    for (int i = 0; i < 32; i++) {
        int idx = tid + i * 128;        // 4096 quads = 128 x 32
        int r   = idx >> 5;
        int c4  = (idx & 31) << 2;
        float4 v = *(float4*)&stg[r * 132 + c4];
        float4 bv = *(const float4*)&bp[nseg + c4];
        v.x += bv.x; v.y += bv.y; v.z += bv.z; v.w += bv.w;

        if (LAYOUT == 0) {
            float* C = (float*)Cv;
            *(float4*)&C[(size_t)(m0 + r) * DMODEL + n0 + c4] = v;
        } else {
            __half* C = (__half*)Cv;
            int m  = m0 + r;
            int bb = m >> 13;
            int ss = m & (SEQ - 1);
            int nl = nseg + c4;
            int hh = nl >> 6;
            int d0 = nl & 63;
            __half2 lo = __floats2half2_rn(v.x, v.y);
            __half2 hi = __floats2half2_rn(v.z, v.w);
            uint2 o; o.x = *(uint32_t*)&lo; o.y = *(uint32_t*)&hi;
            *(uint2*)&C[(size_t)which * QKV_SEG +
                        (((size_t)bb * NHEADS + hh) * SEQ + ss) * HD + d0] = o;
        }
    }
}

// ---------------------------------------------------------------------------
// Pipelined streaming fp16 attention (validated round-10 version).
// ---------------------------------------------------------------------------
#define WKB 64
#define NJ  6
#define SCLD 68
#define PLD  72
#define KVLD 72
#define KVBUF_BYTES (2 * WKB * KVLD * 2)          // 18432
#define OFF_PH  (128 * SCLD * 4)                  // 34816
#define OFF_KV0 (OFF_PH + 128 * PLD * 2)          // 53248
#define OFF_KV1 (OFF_KV0 + KVBUF_BYTES)           // 71680
#define OFF_RS  (OFF_KV1 + KVBUF_BYTES)           // 90112
#define ATTN_SMEM (OFF_RS + 512)                  // 90624

__global__ void __launch_bounds__(256)
attn_kernel(const __half* __restrict__ Q, const __half* __restrict__ K,
            const __half* __restrict__ V, __half* __restrict__ O)
{
    extern __shared__ __align__(128) char smem[];
    const uint32_t sbase = smem_u32(smem);
    float*  Sc   = (float*)smem;                  // [128][68]
    __half* Ph   = (__half*)(smem + OFF_PH);      // [128][72]
    float*  rsum = (float*)(smem + OFF_RS);       // [128]

    const int tid  = threadIdx.x;
    const int warp = tid >> 5;
    const int n    = blockIdx.x & 63;
    const int h    = (blockIdx.x >> 6) & 15;
    const int b    = blockIdx.x >> 10;
    const size_t base = ((size_t)(b * NHEADS + h)) * SEQ * HD;
    const int kbase = (n - 1) * BS;

    auto load_kv = [&](int j, uint32_t koff) {
        const int kblk = kbase + j * WKB;
#pragma unroll
        for (int i = 0; i < 2; i++) {
            int idx = tid + i * 256;
            int r = idx >> 3, ch = (idx & 7) << 3;
            int kpos = kblk + r;
            bool ok = (kpos >= 0 && kpos < SEQ);
            uint32_t sz = ok ? 16u : 0u;
            size_t off = ok ? (base + (size_t)kpos * HD + ch) : base;
            CP_ASYNC16Z(koff + (r * KVLD + ch) * 2, K + off, sz);
            CP_ASYNC16Z(koff + WKB * KVLD * 2 + (r * KVLD + ch) * 2, V + off, sz);
        }
    };

    {
        const __half* qb = Q + base + (size_t)(n * BS) * HD;
#pragma unroll
        for (int i = 0; i < 4; i++) {
            int idx = tid + i * 256;
            int r = idx >> 3, ch = (idx & 7) << 3;
            *(uint4*)(Ph + r * PLD + ch) = *(const uint4*)(qb + (size_t)r * HD + ch);
        }
    }
    __syncthreads();

    wmma::fragment<wmma::matrix_a, 16, 16, 16, __half, wmma::row_major> qf[4];
#pragma unroll
    for (int ks = 0; ks < 4; ks++)
        wmma::load_matrix_sync(qf[ks], Ph + (warp * 16) * PLD + ks * 16, PLD);
    __syncthreads();

    const int qrow = tid >> 1;
    const int par  = tid & 1;
    int klo = qrow;
    if (kbase < 0 && -kbase > klo) klo = -kbase;
    int khi = qrow + 256;
    {
        int lim = SEQ - kbase - 1;
        if (lim < khi) khi = lim;
    }
    float lsum = 0.f;

    wmma::fragment<wmma::accumulator, 16, 16, 16, float> of[4];
#pragma unroll
    for (int dt = 0; dt < 4; dt++) wmma::fill_fragment(of[dt], 0.0f);

    load_kv(0, sbase + OFF_KV0);
    CP_COMMIT();

    for (int j = 0; j < NJ; j++) {
        const uint32_t koff = sbase + ((j & 1) ? OFF_KV1 : OFF_KV0);

        CP_WAIT(0);
        __syncthreads();

        if (j + 1 < NJ) {
            load_kv(j + 1, sbase + (((j + 1) & 1) ? OFF_KV1 : OFF_KV0));
            CP_COMMIT();
        }

        const __half* Kb = (const __half*)(smem + (koff - sbase));
        const __half* Vb = Kb + WKB * KVLD;

#pragma unroll
        for (int nt = 0; nt < 4; nt++) {
            wmma::fragment<wmma::accumulator, 16, 16, 16, float> sacc;
            wmma::fill_fragment(sacc, 0.0f);
#pragma unroll
            for (int ks = 0; ks < 4; ks++) {
                wmma::fragment<wmma::matrix_b, 16, 16, 16, __half, wmma::col_major> bf;
                wmma::load_matrix_sync(bf, Kb + (nt * 16) * KVLD + ks * 16, KVLD);
                wmma::mma_sync(sacc, qf[ks], bf, sacc);
            }
            wmma::store_matrix_sync(&Sc[(warp * 16) * SCLD + nt * 16], sacc,
                                    SCLD, wmma::mem_row_major);
        }
        __syncwarp();

        {
            float* row = &Sc[qrow * SCLD];
            __half* prow = Ph + qrow * PLD;
            const int c0 = par * 32;
#pragma unroll
            for (int c4 = 0; c4 < 32; c4 += 4) {
                int c = c0 + c4;
                float4 v = *(float4*)&row[c];
                float p0 = 0.f, p1 = 0.f, p2 = 0.f, p3 = 0.f;
                int kk = j * WKB + c;
                if (kk + 0 >= klo && kk + 0 <= khi) p0 = __expf(v.x * 0.125f);
                if (kk + 1 >= klo && kk + 1 <= khi) p1 = __expf(v.y * 0.125f);
                if (kk + 2 >= klo && kk + 2 <= khi) p2 = __expf(v.z * 0.125f);
                if (kk + 3 >= klo && kk + 3 <= khi) p3 = __expf(v.w * 0.125f);
                lsum += p0 + p1 + p2 + p3;
                __half2 lo = __floats2half2_rn(p0, p1);
                __half2 hi = __floats2half2_rn(p2, p3);
                uint2 o; o.x = *(uint32_t*)&lo; o.y = *(uint32_t*)&hi;
                *(uint2*)&prow[c] = o;
            }
        }
        __syncwarp();

#pragma unroll
        for (int ks = 0; ks < 4; ks++) {
            wmma::fragment<wmma::matrix_a, 16, 16, 16, __half, wmma::row_major> pf;
            wmma::load_matrix_sync(pf, Ph + (warp * 16) * PLD + ks * 16, PLD);
#pragma unroll
            for (int dt = 0; dt < 4; dt++) {
                wmma::fragment<wmma::matrix_b, 16, 16, 16, __half, wmma::row_major> vf;
                wmma::load_matrix_sync(vf, Vb + (ks * 16) * KVLD + dt * 16, KVLD);
                wmma::mma_sync(of[dt], pf, vf, of[dt]);
            }
        }
    }

    lsum += __shfl_xor_sync(0xFFFFFFFF, lsum, 1);
    if (par == 0) rsum[qrow] = 1.0f / lsum;

#pragma unroll
    for (int dt = 0; dt < 4; dt++)
        wmma::store_matrix_sync(&Sc[(warp * 16) * SCLD + dt * 16], of[dt],
                                SCLD, wmma::mem_row_major);
    __syncthreads();

#pragma unroll
    for (int i = 0; i < 4; i++) {
        int idx = tid + i * 256;
        int r = idx >> 3, ch = (idx & 7) << 3;
        float s = rsum[r];
        float4 f0 = *(float4*)&Sc[r * SCLD + ch];
        float4 f1 = *(float4*)&Sc[r * SCLD + ch + 4];
        __half2 a = __floats2half2_rn(f0.x * s, f0.y * s);
        __half2 bb2 = __floats2half2_rn(f0.z * s, f0.w * s);
        __half2 cc = __floats2half2_rn(f1.x * s, f1.y * s);
        __half2 d = __floats2half2_rn(f1.z * s, f1.w * s);
        uint4 o;
        o.x = *(uint32_t*)&a; o.y = *(uint32_t*)&bb2;
        o.z = *(uint32_t*)&cc; o.w = *(uint32_t*)&d;
        *(uint4*)&O[((size_t)b * SEQ + (size_t)n * BS + r) * DMODEL + h * HD + ch] = o;
    }
}

// ---------------------------------------------------------------------------
// Launch
// ---------------------------------------------------------------------------
extern "C" void kernel_launch(void* const* d_in, const int* in_sizes, int n_in,
                              void* d_out, int out_size)
{
    const float* x  = (const float*)d_in[0];
    const float* Wq = (const float*)d_in[1];
    const float* bq = (const float*)d_in[2];
    const float* Wk = (const float*)d_in[3];
    const float* bk = (const float*)d_in[4];
    const float* Wv = (const float*)d_in[5];
    const float* bv = (const float*)d_in[6];
    const float* Wo = (const float*)d_in[7];
    const float* bo = (const float*)d_in[8];
    float* out = (float*)d_out;

    __half *xh, *wqkv, *wo, *ah, *qkv;
    cudaGetSymbolAddress((void**)&xh,   g_xh);
    cudaGetSymbolAddress((void**)&wqkv, g_wqkv);
    cudaGetSymbolAddress((void**)&wo,   g_wo);
    cudaGetSymbolAddress((void**)&ah,   g_attnh);
    cudaGetSymbolAddress((void**)&qkv,  g_qkvh);

    cudaFuncSetAttribute(gemm_h_kernel<0>,
                         cudaFuncAttributeMaxDynamicSharedMemorySize, GEMM_SMEM);
    cudaFuncSetAttribute(gemm_h_kernel<1>,
                         cudaFuncAttributeMaxDynamicSharedMemorySize, GEMM_SMEM);
    cudaFuncSetAttribute(attn_kernel,
                         cudaFuncAttributeMaxDynamicSharedMemorySize, ATTN_SMEM);

    // single merged conversion launch (x + all 4 weights)
    convert_all_kernel<<<2048, 256>>>(x, Wq, Wk, Wv, Wo);

    // Fused QKV projection: N = 3072
    dim3 qgrid(3 * DMODEL / 128, (BATCH * SEQ) / 128);   // (24,128)
    gemm_h_kernel<1><<<qgrid, 128, GEMM_SMEM>>>(xh, wqkv, bq, bk, bv, qkv);

    attn_kernel<<<BATCH * NHEADS * NBLK, 256, ATTN_SMEM>>>(
        qkv, qkv + QKV_SEG, qkv + 2 * QKV_SEG, ah);

    dim3 ogrid(DMODEL / 128, (BATCH * SEQ) / 128);       // (8,128)
    gemm_h_kernel<0><<<ogrid, 128, GEMM_SMEM>>>(ah, wo, bo, bo, bo, out);
}

// round 14
// speedup vs baseline: 1.0567x; 1.0121x over previous
#include <cuda_runtime.h>
#include <cuda_fp16.h>
#include <mma.h>
#include <cstdint>

using namespace nvcuda;

#define BATCH   2
#define SEQ     8192
#define DMODEL  1024
#define NHEADS  16
#define HD      64
#define NBLK    64
#define BS      128

#define QKV_SEG ((size_t)BATCH * NHEADS * SEQ * HD)   // 16M halves per segment

// ---------------------------------------------------------------------------
// Device scratch
// ---------------------------------------------------------------------------
__device__ __half g_xh[(size_t)BATCH * SEQ * DMODEL];      // fp16 x
__device__ __half g_wqkv[(size_t)3 * DMODEL * DMODEL];     // Wq|Wk|Wv concat (N-dim)
__device__ __half g_wo[(size_t)DMODEL * DMODEL];
__device__ __half g_qkvh[3 * QKV_SEG];                     // q|k|v fp16
__device__ __half g_attnh[(size_t)BATCH * SEQ * DMODEL];   // fp16 attn out

// ---------------------------------------------------------------------------
// merged conversion kernel: x -> g_xh, Wq|Wk|Wv -> g_wqkv, Wo -> g_wo
// ---------------------------------------------------------------------------
#define XN4 ((BATCH * SEQ * DMODEL) / 4)          // 4194304
#define WN4 ((DMODEL * DMODEL) / 4)               // 262144
#define TOTAL4 (XN4 + 4 * WN4)

__global__ void convert_all_kernel(const float* __restrict__ x,
                                   const float* __restrict__ Wq,
                                   const float* __restrict__ Wk,
                                   const float* __restrict__ Wv,
                                   const float* __restrict__ Wo)
{
    int i = blockIdx.x * blockDim.x + threadIdx.x;
    for (; i < TOTAL4; i += gridDim.x * blockDim.x) {
        const float* src;
        __half* dst;
        int loc;
        if (i < XN4) {
            src = x; dst = g_xh; loc = i;
        } else if (i < XN4 + 3 * WN4) {
            int j = i - XN4;
            int which = j / WN4;
            loc = j - which * WN4;
            src = (which == 0) ? Wq : (which == 1) ? Wk : Wv;
            dst = g_wqkv + (size_t)which * (DMODEL * DMODEL);
        } else {
            loc = i - XN4 - 3 * WN4;
            src = Wo; dst = g_wo;
        }
        float4 v = *(const float4*)(src + (size_t)loc * 4);
        __half2 lo = __floats2half2_rn(v.x, v.y);
        __half2 hi = __floats2half2_rn(v.z, v.w);
        uint2 o;
        o.x = *(uint32_t*)&lo;
        o.y = *(uint32_t*)&hi;
        *(uint2*)(dst + (size_t)loc * 4) = o;
    }
}

// ---------------------------------------------------------------------------
// cp.async helpers
// ---------------------------------------------------------------------------
__device__ __forceinline__ uint32_t smem_u32(const void* p) {
    uint32_t a;
    asm("{ .reg .u64 t; cvta.to.shared.u64 t, %1; cvt.u32.u64 %0, t; }" : "=r"(a) : "l"(p));
    return a;
}
#define CP_ASYNC16(dst, src) \
    asm volatile("cp.async.cg.shared.global [%0], [%1], 16;" :: "r"(dst), "l"(src))
#define CP_ASYNC16Z(dst, src, sz) \
    asm volatile("cp.async.cg.shared.global [%0], [%1], 16, %2;" :: "r"(dst), "l"(src), "r"(sz))
#define CP_COMMIT() asm volatile("cp.async.commit_group;")
#define CP_WAIT(N)  asm volatile("cp.async.wait_group %0;" :: "n"(N) : "memory")

// ---------------------------------------------------------------------------
// fp16 GEMM (round-13 banked): BM=BN=128, BK=32, 128 threads, warp 64x64,
// 5-stage cp.async, 102.4KB smem, 2 CTAs/SM.
// ---------------------------------------------------------------------------
#define BKH   32
#define LDH   40
#define NST   5
#define NCH   (DMODEL / BKH)                      // 32
#define TILE_HBYTES (128 * LDH * 2)               // 10240
#define STAGE_BYTES (2 * TILE_HBYTES)             // 20480
#define GEMM_SMEM   (NST * STAGE_BYTES)           // 102400

template <int LAYOUT>
__global__ void __launch_bounds__(128, 2)
gemm_h_kernel(const __half* __restrict__ A, const __half* __restrict__ W,
              const float* __restrict__ b0, const float* __restrict__ b1,
              const float* __restrict__ b2, void* __restrict__ Cv)
{
    extern __shared__ __align__(128) char smem[];
    const uint32_t sbase = smem_u32(smem);
    const int tid  = threadIdx.x;
    const int warp = tid >> 5;
    const int wm   = warp & 1;
    const int wn   = warp >> 1;
    const int m0   = blockIdx.y * 128;
    const int n0   = blockIdx.x * 128;

    const __half* Abase = A + (size_t)m0 * DMODEL;
    const __half* Bbase = W + (size_t)n0 * DMODEL;

    wmma::fragment<wmma::accumulator, 16, 16, 16, float> acc[4][4];
#pragma unroll
    for (int i = 0; i < 4; i++)
#pragma unroll
        for (int j = 0; j < 4; j++)
            wmma::fill_fragment(acc[i][j], 0.0f);

    auto load_stage = [&](int c, int s) {
        const int k0 = c * BKH;
        uint32_t sa = sbase + s * STAGE_BYTES;
#pragma unroll
        for (int i = 0; i < 4; i++) {
            int idx = tid + i * 128;
            int r = idx >> 2, ch = (idx & 3) << 3;
            CP_ASYNC16(sa + (r * LDH + ch) * 2,
                       Abase + (size_t)r * DMODEL + k0 + ch);
        }
#pragma unroll
        for (int i = 0; i < 4; i++) {
            int idx = tid + i * 128;
            int r = idx >> 2, ch = (idx & 3) << 3;
            CP_ASYNC16(sa + TILE_HBYTES + (r * LDH + ch) * 2,
                       Bbase + (size_t)r * DMODEL + k0 + ch);
        }
    };

    load_stage(0, 0); CP_COMMIT();
    load_stage(1, 1); CP_COMMIT();
    load_stage(2, 2); CP_COMMIT();
    load_stage(3, 3); CP_COMMIT();

    for (int c = 0; c < NCH; c++) {
        const int s = c % NST;
        CP_WAIT(3);
        __syncthreads();

        if (c + NST - 1 < NCH) load_stage(c + NST - 1, (c + NST - 1) % NST);
        CP_COMMIT();

        const __half* As = (const __half*)(smem + s * STAGE_BYTES);
        const __half* Bs = (const __half*)(smem + s * STAGE_BYTES + TILE_HBYTES);
#pragma unroll
        for (int ks = 0; ks < BKH / 16; ks++) {
            wmma::fragment<wmma::matrix_a, 16, 16, 16, __half, wmma::row_major> af[4];
#pragma unroll
            for (int i = 0; i < 4; i++)
                wmma::load_matrix_sync(af[i], As + (wm * 64 + i * 16) * LDH + ks * 16, LDH);
#pragma unroll
            for (int j = 0; j < 4; j++) {
                wmma::fragment<wmma::matrix_b, 16, 16, 16, __half, wmma::col_major> bf;
                wmma::load_matrix_sync(bf, Bs + (wn * 64 + j * 16) * LDH + ks * 16, LDH);
#pragma unroll
                for (int i = 0; i < 4; i++)
                    wmma::mma_sync(acc[i][j], af[i], bf, acc[i][j]);
            }
        }
    }

    CP_WAIT(0);
    __syncthreads();

    float* stg = (float*)smem;
#pragma unroll
    for (int i = 0; i < 4; i++)
#pragma unroll
        for (int j = 0; j < 4; j++)
            wmma::store_matrix_sync(&stg[(wm * 64 + i * 16) * 132 + wn * 64 + j * 16],
                                    acc[i][j], 132, wmma::mem_row_major);
    __syncthreads();

    const int which = n0 >> 10;
    const float* bp = (LAYOUT == 0) ? b0
                      : (which == 0 ? b0 : (which == 1 ? b1 : b2));
    const int nseg = (LAYOUT == 0) ? n0 : (n0 & 1023);

#pragma unroll
    for (int i = 0; i < 32; i++) {
        int idx = tid + i * 128;
        int r   = idx >> 5;
        int c4  = (idx & 31) << 2;
        float4 v = *(float4*)&stg[r * 132 + c4];
        float4 bv = *(const float4*)&bp[nseg + c4];
        v.x += bv.x; v.y += bv.y; v.z += bv.z; v.w += bv.w;

        if (LAYOUT == 0) {
            float* C = (float*)Cv;
            *(float4*)&C[(size_t)(m0 + r) * DMODEL + n0 + c4] = v;
        } else {
            __half* C = (__half*)Cv;
            int m  = m0 + r;
            int bb = m >> 13;
            int ss = m & (SEQ - 1);
            int nl = nseg + c4;
            int hh = nl >> 6;
            int d0 = nl & 63;
            __half2 lo = __floats2half2_rn(v.x, v.y);
            __half2 hi = __floats2half2_rn(v.z, v.w);
            uint2 o; o.x = *(uint32_t*)&lo; o.y = *(uint32_t*)&hi;
            *(uint2*)&C[(size_t)which * QKV_SEG +
                        (((size_t)bb * NHEADS + hh) * SEQ + ss) * HD + d0] = o;
        }
    }
}

// ---------------------------------------------------------------------------
// Pipelined streaming fp16 attention — triple-buffered KV, prefetch dist 2.
// SMEM 109KB: Sc[128][68] f32 | Ph[128][72] h | KV[3]{K[64][72]+V[64][72]} | rsum
// ---------------------------------------------------------------------------
#define WKB 64
#define NJ  6
#define SCLD 68
#define PLD  72
#define KVLD 72
#define NKV  3
#define KVBUF_BYTES (2 * WKB * KVLD * 2)          // 18432
#define OFF_PH  (128 * SCLD * 4)                  // 34816
#define OFF_KV  (OFF_PH + 128 * PLD * 2)          // 53248
#define OFF_RS  (OFF_KV + NKV * KVBUF_BYTES)      // 108544
#define ATTN_SMEM (OFF_RS + 512)                  // 109056

__global__ void __launch_bounds__(256)
attn_kernel(const __half* __restrict__ Q, const __half* __restrict__ K,
            const __half* __restrict__ V, __half* __restrict__ O)
{
    extern __shared__ __align__(128) char smem[];
    const uint32_t sbase = smem_u32(smem);
    float*  Sc   = (float*)smem;                  // [128][68]
    __half* Ph   = (__half*)(smem + OFF_PH);      // [128][72]
    float*  rsum = (float*)(smem + OFF_RS);       // [128]

    const int tid  = threadIdx.x;
    const int warp = tid >> 5;
    const int n    = blockIdx.x & 63;
    const int h    = (blockIdx.x >> 6) & 15;
    const int b    = blockIdx.x >> 10;
    const size_t base = ((size_t)(b * NHEADS + h)) * SEQ * HD;
    const int kbase = (n - 1) * BS;

    auto load_kv = [&](int j) {
        const uint32_t koff = sbase + OFF_KV + (j % NKV) * KVBUF_BYTES;
        const int kblk = kbase + j * WKB;
#pragma unroll
        for (int i = 0; i < 2; i++) {
            int idx = tid + i * 256;
            int r = idx >> 3, ch = (idx & 7) << 3;
            int kpos = kblk + r;
            bool ok = (kpos >= 0 && kpos < SEQ);
            uint32_t sz = ok ? 16u : 0u;
            size_t off = ok ? (base + (size_t)kpos * HD + ch) : base;
            CP_ASYNC16Z(koff + (r * KVLD + ch) * 2, K + off, sz);
            CP_ASYNC16Z(koff + WKB * KVLD * 2 + (r * KVLD + ch) * 2, V + off, sz);
        }
    };

    // Issue KV block 0/1 loads FIRST — latency hides behind Q staging
    load_kv(0); CP_COMMIT();
    load_kv(1); CP_COMMIT();

    // ---- Q (half) -> smem -> fragments ----
    {
        const __half* qb = Q + base + (size_t)(n * BS) * HD;
#pragma unroll
        for (int i = 0; i < 4; i++) {
            int idx = tid + i * 256;
            int r = idx >> 3, ch = (idx & 7) << 3;
            *(uint4*)(Ph + r * PLD + ch) = *(const uint4*)(qb + (size_t)r * HD + ch);
        }
    }
    __syncthreads();

    wmma::fragment<wmma::matrix_a, 16, 16, 16, __half, wmma::row_major> qf[4];
#pragma unroll
    for (int ks = 0; ks < 4; ks++)
        wmma::load_matrix_sync(qf[ks], Ph + (warp * 16) * PLD + ks * 16, PLD);
    __syncthreads();   // Ph free for P reuse

    const int qrow = tid >> 1;
    const int par  = tid & 1;
    int klo = qrow;
    if (kbase < 0 && -kbase > klo) klo = -kbase;
    int khi = qrow + 256;
    {
        int lim = SEQ - kbase - 1;
        if (lim < khi) khi = lim;
    }
    float lsum = 0.f;

    wmma::fragment<wmma::accumulator, 16, 16, 16, float> of[4];
#pragma unroll
    for (int dt = 0; dt < 4; dt++) wmma::fill_fragment(of[dt], 0.0f);

    for (int j = 0; j < NJ; j++) {
        // Block j's group is complete when <=1 group pends (latest holds j+1 /
        // empties). Unconditional commit below keeps the count exact in the tail.
        CP_WAIT(1);
        __syncthreads();     // also orders reuse of buffer (j+2)%3 (readers of
                             // it were at iter j-1 and have all arrived here)

        if (j + 2 < NJ) load_kv(j + 2);
        CP_COMMIT();         // unconditional (possibly empty group)

        const __half* Kb = (const __half*)(smem + OFF_KV + (j % NKV) * KVBUF_BYTES);
        const __half* Vb = Kb + WKB * KVLD;

        // ---- S_j = Q @ K_j^T ----
#pragma unroll
        for (int nt = 0; nt < 4; nt++) {
            wmma::fragment<wmma::accumulator, 16, 16, 16, float> sacc;
            wmma::fill_fragment(sacc, 0.0f);
#pragma unroll
            for (int ks = 0; ks < 4; ks++) {
                wmma::fragment<wmma::matrix_b, 16, 16, 16, __half, wmma::col_major> bf;
                wmma::load_matrix_sync(bf, Kb + (nt * 16) * KVLD + ks * 16, KVLD);
                wmma::mma_sync(sacc, qf[ks], bf, sacc);
            }
            wmma::store_matrix_sync(&Sc[(warp * 16) * SCLD + nt * 16], sacc,
                                    SCLD, wmma::mem_row_major);
        }
        __syncwarp();

        // ---- exp + mask -> P halves; row sums ----
        {
            float* row = &Sc[qrow * SCLD];
            __half* prow = Ph + qrow * PLD;
            const int c0 = par * 32;
#pragma unroll
            for (int c4 = 0; c4 < 32; c4 += 4) {
                int c = c0 + c4;
                float4 v = *(float4*)&row[c];
                float p0 = 0.f, p1 = 0.f, p2 = 0.f, p3 = 0.f;
                int kk = j * WKB + c;
                if (kk + 0 >= klo && kk + 0 <= khi) p0 = __expf(v.x * 0.125f);
                if (kk + 1 >= klo && kk + 1 <= khi) p1 = __expf(v.y * 0.125f);
                if (kk + 2 >= klo && kk + 2 <= khi) p2 = __expf(v.z * 0.125f);
                if (kk + 3 >= klo && kk + 3 <= khi) p3 = __expf(v.w * 0.125f);
                lsum += p0 + p1 + p2 + p3;
                __half2 lo = __floats2half2_rn(p0, p1);
                __half2 hi = __floats2half2_rn(p2, p3);
                uint2 o; o.x = *(uint32_t*)&lo; o.y = *(uint32_t*)&hi;
                *(uint2*)&prow[c] = o;
            }
        }
        __syncwarp();

        // ---- O += P_j @ V_j ----
#pragma unroll
        for (int ks = 0; ks < 4; ks++) {
            wmma::fragment<wmma::matrix_a, 16, 16, 16, __half, wmma::row_major> pf;
            wmma::load_matrix_sync(pf, Ph + (warp * 16) * PLD + ks * 16, PLD);
#pragma unroll
            for (int dt = 0; dt < 4; dt++) {
                wmma::fragment<wmma::matrix_b, 16, 16, 16, __half, wmma::row_major> vf;
                wmma::load_matrix_sync(vf, Vb + (ks * 16) * KVLD + dt * 16, KVLD);
                wmma::mma_sync(of[dt], pf, vf, of[dt]);
            }
        }
    }

    lsum += __shfl_xor_sync(0xFFFFFFFF, lsum, 1);
    if (par == 0) rsum[qrow] = 1.0f / lsum;

#pragma unroll
    for (int dt = 0; dt < 4; dt++)
        wmma::store_matrix_sync(&Sc[(warp * 16) * SCLD + dt * 16], of[dt],
                                SCLD, wmma::mem_row_major);
    __syncthreads();

#pragma unroll
    for (int i = 0; i < 4; i++) {
        int idx = tid + i * 256;
        int r = idx >> 3, ch = (idx & 7) << 3;
        float s = rsum[r];
        float4 f0 = *(float4*)&Sc[r * SCLD + ch];
        float4 f1 = *(float4*)&Sc[r * SCLD + ch + 4];
        __half2 a = __floats2half2_rn(f0.x * s, f0.y * s);
        __half2 bb2 = __floats2half2_rn(f0.z * s, f0.w * s);
        __half2 cc = __floats2half2_rn(f1.x * s, f1.y * s);
        __half2 d = __floats2half2_rn(f1.z * s, f1.w * s);
        uint4 o;
        o.x = *(uint32_t*)&a; o.y = *(uint32_t*)&bb2;
        o.z = *(uint32_t*)&cc; o.w = *(uint32_t*)&d;
        *(uint4*)&O[((size_t)b * SEQ + (size_t)n * BS + r) * DMODEL + h * HD + ch] = o;
    }
}

// ---------------------------------------------------------------------------
// Launch
// ---------------------------------------------------------------------------
extern "C" void kernel_launch(void* const* d_in, const int* in_sizes, int n_in,
                              void* d_out, int out_size)
{
    const float* x  = (const float*)d_in[0];
    const float* Wq = (const float*)d_in[1];
    const float* bq = (const float*)d_in[2];
    const float* Wk = (const float*)d_in[3];
    const float* bk = (const float*)d_in[4];
    const float* Wv = (const float*)d_in[5];
    const float* bv = (const float*)d_in[6];
    const float* Wo = (const float*)d_in[7];
    const float* bo = (const float*)d_in[8];
    float* out = (float*)d_out;

    __half *xh, *wqkv, *wo, *ah, *qkv;
    cudaGetSymbolAddress((void**)&xh,   g_xh);
    cudaGetSymbolAddress((void**)&wqkv, g_wqkv);
    cudaGetSymbolAddress((void**)&wo,   g_wo);
    cudaGetSymbolAddress((void**)&ah,   g_attnh);
    cudaGetSymbolAddress((void**)&qkv,  g_qkvh);

    cudaFuncSetAttribute(gemm_h_kernel<0>,
                         cudaFuncAttributeMaxDynamicSharedMemorySize, GEMM_SMEM);
    cudaFuncSetAttribute(gemm_h_kernel<1>,
                         cudaFuncAttributeMaxDynamicSharedMemorySize, GEMM_SMEM);
    cudaFuncSetAttribute(attn_kernel,
                         cudaFuncAttributeMaxDynamicSharedMemorySize, ATTN_SMEM);

    convert_all_kernel<<<2048, 256>>>(x, Wq, Wk, Wv, Wo);

    dim3 qgrid(3 * DMODEL / 128, (BATCH * SEQ) / 128);   // (24,128)
    gemm_h_kernel<1><<<qgrid, 128, GEMM_SMEM>>>(xh, wqkv, bq, bk, bv, qkv);

    attn_kernel<<<BATCH * NHEADS * NBLK, 256, ATTN_SMEM>>>(
        qkv, qkv + QKV_SEG, qkv + 2 * QKV_SEG, ah);

    dim3 ogrid(DMODEL / 128, (BATCH * SEQ) / 128);       // (8,128)
    gemm_h_kernel<0><<<ogrid, 128, GEMM_SMEM>>>(ah, wo, bo, bo, bo, out);
}